// round 16
// baseline (speedup 1.0000x reference)
#include <cuda_runtime.h>
#include <cuda_fp16.h>
#include <math.h>

#define B_   2048
#define N_   128
#define D_   512
#define HID_ 2048
#define H_   8
#define DH_  64

typedef unsigned long long ull;
typedef __half hf;

// ---------------- scratch ----------------
__device__ float g_wq[B_*H_*D_];
__device__ float g_ctx[B_*D_];
__device__ float g_part[4*B_*D_];
__device__ float g_ps [16*HID_], g_psq[16*HID_];
__device__ float g_scale[HID_], g_shift[HID_];
__device__ float g_b2p[HID_];
__device__ float g_b2part[16*HID_];

__device__ hf g_cath[B_*D_];
__device__ hf g_W1th[HID_*D_];
__device__ hf g_W2th[HID_*HID_];
__device__ hf g_X1h [B_*HID_];
__device__ hf g_X2h [B_*HID_];
__device__ hf g_W3th[D_*HID_];
__device__ hf g_embh[B_*D_],  g_embl[B_*D_];
__device__ hf g_qh  [B_*D_],  g_ql  [B_*D_];
__device__ hf g_uh  [B_*H_*D_], g_ul[B_*H_*D_];
__device__ hf g_Wqth[D_*D_];
__device__ hf g_Woth[D_*D_];
__device__ hf g_Wkh [D_*D_];
__device__ hf g_WvT [H_*128*D_];          // per-head transposed Wv, rows 64..127 zero
__device__ hf g_ctxh[B_*D_], g_ctxl[B_*D_];

// ---------------- PTX helpers ----------------
__device__ __forceinline__ void mma16816(float* c, const unsigned* a, unsigned b0, unsigned b1) {
    asm volatile("mma.sync.aligned.m16n8k16.row.col.f32.f16.f16.f32 "
        "{%0,%1,%2,%3}, {%4,%5,%6,%7}, {%8,%9}, {%0,%1,%2,%3};"
        : "+f"(c[0]), "+f"(c[1]), "+f"(c[2]), "+f"(c[3])
        : "r"(a[0]), "r"(a[1]), "r"(a[2]), "r"(a[3]), "r"(b0), "r"(b1));
}
__device__ __forceinline__ void ldsm4(unsigned* r, unsigned a) {
    asm volatile("ldmatrix.sync.aligned.m8n8.x4.shared.b16 {%0,%1,%2,%3}, [%4];"
        : "=r"(r[0]), "=r"(r[1]), "=r"(r[2]), "=r"(r[3]) : "r"(a));
}
__device__ __forceinline__ void cpasync16(unsigned s, const void* g) {
    asm volatile("cp.async.cg.shared.global [%0], [%1], 16;" :: "r"(s), "l"(g));
}
#define CPCOMMIT() asm volatile("cp.async.commit_group;" ::: "memory")
#define CPWAIT0()  asm volatile("cp.async.wait_group 0;" ::: "memory")

__device__ __forceinline__ hf f2h(float v) { return __float2half_rn(v); }
__device__ __forceinline__ float h2f(hf v) { return __half2float(v); }

#define ASTR  40
#define OPTILE (128*ASTR)
#define BUFBF  (4*OPTILE)
#define BUFBYTES (BUFBF*2)
#define SMEMM  (2*BUFBYTES)

// ---------------- HMMA GEMM ----------------
// A fp16 [*, ldKA] rm (hi, + lo if PASSES==2); B fp16 [*, ldKB] rm (hi only).
// PASSES: 1 = AhBh; 2 = AhBh + AlBh.
// MODE 0: plain.  MODE 1: split-K — z covers K-chunk z, raw fp32 partials to
//   Cf + z*M*Nfull.  MODE 2: z-batch — A koff=z*kAstep, B koff=z*kBstep and
//   row offset z*zBstep, C/bias column offset z*cstep; cols >= nvalid skipped.
template<int ACT, int OUTH, int PASSES, int MODE>
__global__ __launch_bounds__(256) void gemm_mma(
    const hf* __restrict__ Ah_, const hf* __restrict__ Al_,
    const hf* __restrict__ Bh_,
    float* __restrict__ Cf, hf* __restrict__ Ch, hf* __restrict__ Cl,
    const float* __restrict__ bias, int K, int ldKA, int ldKB, int Nfull,
    int kAstep, int kBstep, int zBstep, int cstep, int nvalid)
{
    extern __shared__ hf sm[];
    const int t = threadIdx.x, lane = t & 31, wid = t >> 5;
    const int wm = wid & 3, wn = wid >> 2;
    const int g = lane >> 2, tid4 = lane & 3;
    const int row0 = blockIdx.y * 128, col0 = blockIdx.x * 128;
    const int z = blockIdx.z;
    const int koffA = (MODE == 1) ? z * K : (MODE == 2 ? z * kAstep : 0);
    const int koffB = (MODE == 1) ? z * K : (MODE == 2 ? z * kBstep : 0);
    const unsigned sbase = (unsigned)__cvta_generic_to_shared(sm);

    float acc[2][8][4];
#pragma unroll
    for (int i = 0; i < 2; i++)
#pragma unroll
        for (int j = 0; j < 8; j++)
#pragma unroll
            for (int k = 0; k < 4; k++) acc[i][j][k] = 0.f;

    const int lrow = t >> 1, lhalf = t & 1;
    const hf* Bbase = Bh_ + (MODE == 2 ? (size_t)z * zBstep : 0);
    const unsigned sdst = sbase + (unsigned)((lrow * ASTR) * 2) + lhalf * 32;
    auto issue = [&](int kc, int buf) {
        const size_t ga = (size_t)(row0 + lrow) * ldKA + koffA + kc * 32 + lhalf * 16;
        const size_t gb = (size_t)(col0 + lrow) * ldKB + koffB + kc * 32 + lhalf * 16;
        const unsigned d = sdst + buf * BUFBYTES;
        cpasync16(d,                 Ah_ + ga);
        cpasync16(d + 16,            Ah_ + ga + 8);
        if (PASSES >= 2) {
            cpasync16(d + OPTILE*2,      Al_ + ga);
            cpasync16(d + OPTILE*2 + 16, Al_ + ga + 8);
        }
        cpasync16(d + OPTILE*4,      Bbase + gb);
        cpasync16(d + OPTILE*4 + 16, Bbase + gb + 8);
    };

    const int arow_l = (lane & 7) + ((lane >> 3) & 1) * 8;
    const int acol_l = (lane >> 4) * 8;
    const unsigned a_base = sbase + (unsigned)(((wm * 32 + arow_l) * ASTR + acol_l) * 2);
    const int brow_l = (lane & 7) + (lane >> 4) * 8;
    const int bcol_l = ((lane >> 3) & 1) * 8;
    const unsigned b_base = sbase + (unsigned)(4 * OPTILE)
                          + (unsigned)(((wn * 64 + brow_l) * ASTR + bcol_l) * 2);

    const int nc = K >> 5;
    issue(0, 0);
    CPCOMMIT();
    CPWAIT0();
    __syncthreads();

    for (int c = 0; c < nc; c++) {
        const int p = c & 1;
        if (c + 1 < nc) { issue(c + 1, p ^ 1); CPCOMMIT(); }

        const unsigned ab = a_base + p * BUFBYTES;
        const unsigned bb = b_base + p * BUFBYTES;
#pragma unroll
        for (int ks = 0; ks < 2; ks++) {
            const unsigned ko = ks * 32;
            unsigned ah[2][4], al[2][4];
#pragma unroll
            for (int mt = 0; mt < 2; mt++) {
                ldsm4(ah[mt], ab + mt * (16 * ASTR * 2) + ko);
                if (PASSES >= 2)
                    ldsm4(al[mt], ab + OPTILE * 2 + mt * (16 * ASTR * 2) + ko);
            }
#pragma unroll
            for (int ntp = 0; ntp < 4; ntp++) {
                unsigned bh4[4];
                ldsm4(bh4, bb + ntp * (16 * ASTR * 2) + ko);
#pragma unroll
                for (int sub = 0; sub < 2; sub++) {
                    const int nt = ntp * 2 + sub;
#pragma unroll
                    for (int mt = 0; mt < 2; mt++) {
                        mma16816(acc[mt][nt], ah[mt], bh4[sub*2], bh4[sub*2+1]);
                        if (PASSES >= 2)
                            mma16816(acc[mt][nt], al[mt], bh4[sub*2], bh4[sub*2+1]);
                    }
                }
            }
        }
        if (c + 1 < nc) {
            CPWAIT0();
            __syncthreads();
        }
    }

    float* Cp = Cf;
    int coladd = 0;
    if (MODE == 1) Cp += (size_t)z * (size_t)(gridDim.y * 128) * Nfull;
    if (MODE == 2) coladd = z * cstep;

#pragma unroll
    for (int mt = 0; mt < 2; mt++) {
#pragma unroll
        for (int nt = 0; nt < 8; nt++) {
            const int r = row0 + wm * 32 + mt * 16 + g;
            const int lc = wn * 64 + nt * 8 + tid4 * 2;
            if (MODE == 2 && lc >= nvalid) continue;
            const int cc = coladd + col0 + lc;
            if (MODE == 1) {
                *(float2*)(Cp + (size_t)r * Nfull + cc) =
                    make_float2(acc[mt][nt][0], acc[mt][nt][1]);
                *(float2*)(Cp + (size_t)(r + 8) * Nfull + cc) =
                    make_float2(acc[mt][nt][2], acc[mt][nt][3]);
                continue;
            }
            float v0 = acc[mt][nt][0], v1 = acc[mt][nt][1];
            float v2 = acc[mt][nt][2], v3 = acc[mt][nt][3];
            if (bias) { v0 += bias[cc]; v1 += bias[cc+1]; v2 += bias[cc]; v3 += bias[cc+1]; }
            if (ACT) { v0 = tanhf(v0); v1 = tanhf(v1); v2 = tanhf(v2); v3 = tanhf(v3); }
            if (OUTH) {
                hf h0 = f2h(v0), h1 = f2h(v1), h2 = f2h(v2), h3 = f2h(v3);
                *(half2*)(Ch + (size_t)r * Nfull + cc)       = half2(h0, h1);
                *(half2*)(Ch + (size_t)(r + 8) * Nfull + cc) = half2(h2, h3);
                if (Cl) {
                    *(half2*)(Cl + (size_t)r * Nfull + cc) =
                        half2(f2h(v0 - h2f(h0)), f2h(v1 - h2f(h1)));
                    *(half2*)(Cl + (size_t)(r + 8) * Nfull + cc) =
                        half2(f2h(v2 - h2f(h2)), f2h(v3 - h2f(h3)));
                }
            } else {
                *(float2*)(Cp + (size_t)r * Nfull + cc)       = make_float2(v0, v1);
                *(float2*)(Cp + (size_t)(r + 8) * Nfull + cc) = make_float2(v2, v3);
            }
        }
    }
}

// ---------------- split-K reduces ----------------
__global__ __launch_bounds__(256) void reduce4_f32(const float* __restrict__ part,
                                                   float* __restrict__ out,
                                                   const float* __restrict__ bias,
                                                   int total, int ldc)
{
    const int i = (blockIdx.x * 256 + threadIdx.x) * 4;
    if (i >= total) return;
    float4 v0 = *(const float4*)(part + i);
    float4 v1 = *(const float4*)(part + (size_t)total   + i);
    float4 v2 = *(const float4*)(part + (size_t)total*2 + i);
    float4 v3 = *(const float4*)(part + (size_t)total*3 + i);
    const int c = i % ldc;
    float4 r;
    r.x = (v0.x + v1.x) + (v2.x + v3.x) + bias[c+0];
    r.y = (v0.y + v1.y) + (v2.y + v3.y) + bias[c+1];
    r.z = (v0.z + v1.z) + (v2.z + v3.z) + bias[c+2];
    r.w = (v0.w + v1.w) + (v2.w + v3.w) + bias[c+3];
    *(float4*)(out + i) = r;
}

__global__ __launch_bounds__(256) void reduce4_hilo(const float* __restrict__ part,
                                                    hf* __restrict__ oh, hf* __restrict__ ol,
                                                    const float* __restrict__ bias,
                                                    int total, int ldc)
{
    const int i = (blockIdx.x * 256 + threadIdx.x) * 4;
    if (i >= total) return;
    float4 v0 = *(const float4*)(part + i);
    float4 v1 = *(const float4*)(part + (size_t)total   + i);
    float4 v2 = *(const float4*)(part + (size_t)total*2 + i);
    float4 v3 = *(const float4*)(part + (size_t)total*3 + i);
    const int c = i % ldc;
    float r0 = (v0.x + v1.x) + (v2.x + v3.x) + bias[c+0];
    float r1 = (v0.y + v1.y) + (v2.y + v3.y) + bias[c+1];
    float r2 = (v0.z + v1.z) + (v2.z + v3.z) + bias[c+2];
    float r3 = (v0.w + v1.w) + (v2.w + v3.w) + bias[c+3];
    hf h0=f2h(r0), h1=f2h(r1), h2=f2h(r2), h3=f2h(r3);
    *(half2*)(oh+i)   = half2(h0,h1);
    *(half2*)(oh+i+2) = half2(h2,h3);
    *(half2*)(ol+i)   = half2(f2h(r0-h2f(h0)), f2h(r1-h2f(h1)));
    *(half2*)(ol+i+2) = half2(f2h(r2-h2f(h2)), f2h(r3-h2f(h3)));
}

// ---------------- conversions ----------------
__global__ __launch_bounds__(256) void conv_split(const float* __restrict__ in,
                                                  hf* __restrict__ oh, hf* __restrict__ ol, int n)
{
    const int i = (blockIdx.x * 256 + threadIdx.x) * 4;
    if (i >= n) return;
    float4 v = *(const float4*)(in + i);
    hf h0=f2h(v.x), h1=f2h(v.y), h2=f2h(v.z), h3=f2h(v.w);
    *(half2*)(oh+i)   = half2(h0,h1);
    *(half2*)(oh+i+2) = half2(h2,h3);
    if (ol) {
        *(half2*)(ol+i)   = half2(f2h(v.x-h2f(h0)), f2h(v.y-h2f(h1)));
        *(half2*)(ol+i+2) = half2(f2h(v.z-h2f(h2)), f2h(v.w-h2f(h3)));
    }
}

template<int SCALE>
__global__ __launch_bounds__(256) void conv_tsplit(const float* __restrict__ in,
                                                   hf* __restrict__ oh, int K, int N)
{
    __shared__ float tile[32][33];
    const int n0 = blockIdx.x * 32, k0 = blockIdx.y * 32;
    const int c = threadIdx.x & 31, r = threadIdx.x >> 5;
#pragma unroll
    for (int rr = 0; rr < 4; rr++)
        tile[r + rr*8][c] = in[(size_t)(k0 + r + rr*8) * N + n0 + c];
    __syncthreads();
    const float sck = SCALE ? g_scale[k0 + c] : 1.f;
#pragma unroll
    for (int rr = 0; rr < 4; rr++) {
        const int row = r + rr*8;
        oh[(size_t)(n0 + row) * K + k0 + c] = f2h(tile[c][row] * sck);
    }
}

// per-head transposed Wv, padded to 128 rows: WvT[h*128+cc][c] = Wv[c][h*64+cc] (cc<64)
__global__ __launch_bounds__(256) void wvt_k(const float* __restrict__ Wv, hf* __restrict__ out)
{
    __shared__ float tile[32][33];
    const int c0 = blockIdx.x * 32, cc0 = blockIdx.y * 32, h = blockIdx.z;
    const int x = threadIdx.x & 31, y = threadIdx.x >> 5;
#pragma unroll
    for (int rr = 0; rr < 4; rr++) {
        const int row = y + rr*8;     // c-index within tile
        float v = 0.f;
        if (cc0 + x < 64) v = Wv[(size_t)(c0 + row) * D_ + h * 64 + cc0 + x];
        tile[row][x] = v;
    }
    __syncthreads();
#pragma unroll
    for (int rr = 0; rr < 4; rr++) {
        const int row = y + rr*8;     // cc-index within tile
        out[(size_t)(h * 128 + cc0 + row) * D_ + c0 + x] = f2h(tile[x][row]);
    }
}

// bias2' = b2 + shift @ W2 — two-stage
__global__ __launch_bounds__(256) void bias2_part(const float* __restrict__ W2)
{
    const int c = blockIdx.x * 256 + threadIdx.x;
    const int k0 = blockIdx.y * 128;
    float s = 0.f;
#pragma unroll 4
    for (int k = 0; k < 128; k++)
        s += g_shift[k0 + k] * W2[(size_t)(k0 + k) * HID_ + c];
    g_b2part[blockIdx.y * HID_ + c] = s;
}
__global__ __launch_bounds__(256) void bias2_fin(const float* __restrict__ b2)
{
    const int c = blockIdx.x * 256 + threadIdx.x;
    float s = b2[c];
#pragma unroll
    for (int i = 0; i < 16; i++) s += g_b2part[i * HID_ + c];
    g_b2p[c] = s;
}

// ---------------- BN ----------------
__global__ void bn_partial()
{
    const int t = threadIdx.x;
    const int col = blockIdx.x * 128 + (t & 127);
    const int rh = t >> 7;
    const int r0 = blockIdx.y * 128 + rh * 64;
    float s = 0.f, sq = 0.f;
    for (int r = 0; r < 64; r++) {
        float v = h2f(g_X1h[(size_t)(r0 + r) * HID_ + col]);
        s += v; sq += v * v;
    }
    __shared__ float sm1[256], sm2[256];
    sm1[t] = s; sm2[t] = sq;
    __syncthreads();
    if (rh == 0) {
        s += sm1[t+128]; sq += sm2[t+128];
        g_ps [blockIdx.y * HID_ + col] = s;
        g_psq[blockIdx.y * HID_ + col] = sq;
    }
}
__global__ void bn_finalize(const float* __restrict__ gamma, const float* __restrict__ beta)
{
    const int c = blockIdx.x * 256 + threadIdx.x;
    float s = 0.f, sq = 0.f;
    for (int i = 0; i < 16; i++) { s += g_ps[i*HID_+c]; sq += g_psq[i*HID_+c]; }
    const float mean = s * (1.f/(float)B_);
    const float var  = sq * (1.f/(float)B_) - mean*mean;
    const float sc = gamma[c] * rsqrtf(var + 1e-5f);
    g_scale[c] = sc;
    g_shift[c] = beta[c] - mean * sc;
}

// ---------------- fused single-pass attention (writes u as fp16 hi/lo) -------
__global__ __launch_bounds__(256) void attn_k(const float* __restrict__ nb,
                                              const int* __restrict__ len)
{
    __shared__ float nbt[8 * 544];
    __shared__ float ssum[H_][4];
    const int b = blockIdx.x, t = threadIdx.x;
    const int w = t >> 5, l = t & 31;
    const int hg = w & 1, ng = w >> 1;
    const float* nbb = nb + (size_t)b * N_ * D_;
    const int L = len[b];
    const int ntiles = (L + 7) >> 3;

    float wqf[4][16];
#pragma unroll
    for (int hh = 0; hh < 4; hh++) {
        const float* p = g_wq + (size_t)b * H_ * D_ + (size_t)(hg*4+hh) * D_ + l*16;
#pragma unroll
        for (int j4 = 0; j4 < 4; j4++) {
            float4 v = *(const float4*)(p + j4*4);
            wqf[hh][j4*4+0]=v.x; wqf[hh][j4*4+1]=v.y; wqf[hh][j4*4+2]=v.z; wqf[hh][j4*4+3]=v.w;
        }
    }
    float acc[4][16], se[4];
#pragma unroll
    for (int hh = 0; hh < 4; hh++) { se[hh]=0.f;
#pragma unroll
        for (int j = 0; j < 16; j++) acc[hh][j]=0.f; }

    for (int tile = 0; tile < ntiles; tile++) {
        __syncthreads();
#pragma unroll
        for (int i = 0; i < 4; i++) {
            const int idx = t + i*256, rr = idx >> 7, c4 = idx & 127;
            float4 v = *(const float4*)(nbb + (size_t)(tile*8+rr)*D_ + (c4<<2));
            const int ph = rr*544 + (c4>>2)*17 + (c4&3)*4;
            nbt[ph+0]=v.x; nbt[ph+1]=v.y; nbt[ph+2]=v.z; nbt[ph+3]=v.w;
        }
        __syncthreads();
#pragma unroll
        for (int nn = 0; nn < 2; nn++) {
            const int nr = ng*2+nn, n_glob = tile*8+nr;
            const float* row = nbt + nr*544 + l*17;
            float rv[16];
#pragma unroll
            for (int j = 0; j < 16; j++) rv[j] = row[j];
            float p0=0.f,p1=0.f,p2=0.f,p3=0.f;
#pragma unroll
            for (int j = 0; j < 16; j++) {
                p0 += rv[j]*wqf[0][j]; p1 += rv[j]*wqf[1][j];
                p2 += rv[j]*wqf[2][j]; p3 += rv[j]*wqf[3][j];
            }
#pragma unroll
            for (int off = 16; off; off >>= 1) {
                p0 += __shfl_xor_sync(0xffffffffu,p0,off); p1 += __shfl_xor_sync(0xffffffffu,p1,off);
                p2 += __shfl_xor_sync(0xffffffffu,p2,off); p3 += __shfl_xor_sync(0xffffffffu,p3,off);
            }
            const bool valid = (n_glob < L);
            const float e0 = valid ? __expf(p0*0.125f) : 0.f;
            const float e1 = valid ? __expf(p1*0.125f) : 0.f;
            const float e2 = valid ? __expf(p2*0.125f) : 0.f;
            const float e3 = valid ? __expf(p3*0.125f) : 0.f;
            se[0]+=e0; se[1]+=e1; se[2]+=e2; se[3]+=e3;
#pragma unroll
            for (int j = 0; j < 16; j++) {
                acc[0][j]+=e0*rv[j]; acc[1][j]+=e1*rv[j];
                acc[2][j]+=e2*rv[j]; acc[3][j]+=e3*rv[j];
            }
        }
    }
    __syncthreads();
    if (l == 0)
#pragma unroll
        for (int hh = 0; hh < 4; hh++) ssum[hg*4+hh][ng] = se[hh];

    float* ur = nbt;
    __syncthreads();
    for (int r = 0; r < 4; r++) {
        if (ng == r) {
#pragma unroll
            for (int hh = 0; hh < 4; hh++)
#pragma unroll
                for (int j = 0; j < 16; j++) {
                    const int idx = (hg*4+hh)*D_ + l*16 + j;
                    if (r == 0) ur[idx] = acc[hh][j]; else ur[idx] += acc[hh][j];
                }
        }
        __syncthreads();
    }
    hf* uph = g_uh + (size_t)b * H_ * D_;
    hf* upl = g_ul + (size_t)b * H_ * D_;
    for (int i = t*4; i < H_ * D_; i += 1024) {
        const int h = i >> 9;
        const float inv = 1.f / (ssum[h][0]+ssum[h][1]+ssum[h][2]+ssum[h][3]);
        float4 v = *(const float4*)(ur + i);
        v.x*=inv; v.y*=inv; v.z*=inv; v.w*=inv;
        hf h0=f2h(v.x), h1=f2h(v.y), h2=f2h(v.z), h3=f2h(v.w);
        *(half2*)(uph+i)   = half2(h0,h1);
        *(half2*)(uph+i+2) = half2(h2,h3);
        *(half2*)(upl+i)   = half2(f2h(v.x-h2f(h0)), f2h(v.y-h2f(h1)));
        *(half2*)(upl+i+2) = half2(f2h(v.z-h2f(h2)), f2h(v.w-h2f(h3)));
    }
}

// ---------------- host ----------------
extern "C" void kernel_launch(void* const* d_in, const int* in_sizes, int n_in,
                              void* d_out, int out_size)
{
    const float* catalog  = (const float*)d_in[0];
    const float* neighbors= (const float*)d_in[1];
    const int*   lengths  = (const int*)  d_in[2];
    const float* W1 = (const float*)d_in[3];
    const float* b1 = (const float*)d_in[4];
    const float* gamma = (const float*)d_in[5];
    const float* beta  = (const float*)d_in[6];
    const float* W2 = (const float*)d_in[7];
    const float* b2 = (const float*)d_in[8];
    const float* W3 = (const float*)d_in[9];
    const float* b3 = (const float*)d_in[10];
    const float* Wq = (const float*)d_in[11];
    const float* bq = (const float*)d_in[12];
    const float* Wk = (const float*)d_in[13];
    // d_in[14] = bk cancels in softmax
    const float* Wv = (const float*)d_in[15];
    const float* bv = (const float*)d_in[16];
    const float* Wo = (const float*)d_in[17];
    const float* bo = (const float*)d_in[18];
    float* out = (float*)d_out;

    float *pwq, *pctx, *pb2p, *ppart;
    cudaGetSymbolAddress((void**)&pwq, g_wq);
    cudaGetSymbolAddress((void**)&pctx,g_ctx);
    cudaGetSymbolAddress((void**)&pb2p,g_b2p);
    cudaGetSymbolAddress((void**)&ppart,g_part);
    hf *cath,*W1th,*W2th,*X1h,*X2h,*W3th,*embh,*embl,*qh,*ql,*uh,*ul;
    hf *Wqth,*Woth,*Wkh,*WvT,*ctxh,*ctxl;
    cudaGetSymbolAddress((void**)&cath, g_cath);
    cudaGetSymbolAddress((void**)&W1th, g_W1th);
    cudaGetSymbolAddress((void**)&W2th, g_W2th);
    cudaGetSymbolAddress((void**)&X1h,  g_X1h);
    cudaGetSymbolAddress((void**)&X2h,  g_X2h);
    cudaGetSymbolAddress((void**)&W3th, g_W3th);
    cudaGetSymbolAddress((void**)&embh, g_embh); cudaGetSymbolAddress((void**)&embl, g_embl);
    cudaGetSymbolAddress((void**)&qh,   g_qh);   cudaGetSymbolAddress((void**)&ql,   g_ql);
    cudaGetSymbolAddress((void**)&uh,   g_uh);   cudaGetSymbolAddress((void**)&ul,   g_ul);
    cudaGetSymbolAddress((void**)&Wqth, g_Wqth);
    cudaGetSymbolAddress((void**)&Woth, g_Woth);
    cudaGetSymbolAddress((void**)&Wkh,  g_Wkh);
    cudaGetSymbolAddress((void**)&WvT,  g_WvT);
    cudaGetSymbolAddress((void**)&ctxh, g_ctxh); cudaGetSymbolAddress((void**)&ctxl, g_ctxl);

    cudaFuncSetAttribute(gemm_mma<1,1,1,0>, cudaFuncAttributeMaxDynamicSharedMemorySize, SMEMM);
    cudaFuncSetAttribute(gemm_mma<0,0,1,1>, cudaFuncAttributeMaxDynamicSharedMemorySize, SMEMM);
    cudaFuncSetAttribute(gemm_mma<0,0,2,1>, cudaFuncAttributeMaxDynamicSharedMemorySize, SMEMM);
    cudaFuncSetAttribute(gemm_mma<0,0,2,2>, cudaFuncAttributeMaxDynamicSharedMemorySize, SMEMM);

    const int BD = B_ * D_;
    const int BHD = B_ * H_ * D_;

    // weight/input conversions
    conv_tsplit<0><<<dim3(HID_/32, D_/32), 256>>>(W1, W1th, D_, HID_);
    conv_tsplit<0><<<dim3(D_/32, HID_/32), 256>>>(W3, W3th, HID_, D_);
    conv_tsplit<0><<<dim3(D_/32, D_/32), 256>>>(Wq, Wqth, D_, D_);
    conv_tsplit<0><<<dim3(D_/32, D_/32), 256>>>(Wo, Woth, D_, D_);
    conv_split<<<D_*D_/1024, 256>>>(Wk, Wkh, nullptr, D_*D_);
    wvt_k<<<dim3(D_/32, 4, H_), 256>>>(Wv, WvT);
    conv_split<<<BD/1024, 256>>>(catalog, cath, nullptr, BD);

    // X1 = tanh(cat @ W1 + b1) -> fp16 hi (1-pass)
    gemm_mma<1,1,1,0><<<dim3(HID_/128, B_/128), 256, SMEMM>>>(cath, nullptr, W1th,
        nullptr, X1h, nullptr, b1, D_, D_, D_, HID_, 0,0,0,0, 128);
    bn_partial<<<dim3(16,16), 256>>>();
    bn_finalize<<<8, 256>>>(gamma, beta);
    conv_tsplit<1><<<dim3(HID_/32, HID_/32), 256>>>(W2, W2th, HID_, HID_);
    bias2_part<<<dim3(HID_/256, 16), 256>>>(W2);
    bias2_fin<<<HID_/256, 256>>>(b2);
    // X2 = tanh(X1 @ W2' + b2') (1-pass)
    gemm_mma<1,1,1,0><<<dim3(HID_/128, B_/128), 256, SMEMM>>>(X1h, nullptr, W2th,
        nullptr, X2h, nullptr, pb2p, HID_, HID_, HID_, HID_, 0,0,0,0, 128);
    // emb = X2 @ W3 + b3 — 1-pass, split-K 4
    gemm_mma<0,0,1,1><<<dim3(D_/128, B_/128, 4), 256, SMEMM>>>(X2h, nullptr, W3th,
        ppart, nullptr, nullptr, nullptr, HID_/4, HID_, HID_, D_, 0,0,0,0, 128);
    reduce4_hilo<<<BD/1024, 256>>>(ppart, embh, embl, b3, BD, D_);
    // q = emb @ Wq + bq — 2-pass, split-K 4 -> fp16 hi/lo
    gemm_mma<0,0,2,1><<<dim3(D_/128, B_/128, 4), 256, SMEMM>>>(embh, embl, Wqth,
        ppart, nullptr, nullptr, nullptr, D_/4, D_, D_, D_, 0,0,0,0, 128);
    reduce4_hilo<<<BD/1024, 256>>>(ppart, qh, ql, bq, BD, D_);
    // wq_eff[:, h*512+c] = sum_dh q[:,h*64+dh] * Wk[c, h*64+dh] — mma MODE 2
    gemm_mma<0,0,2,2><<<dim3(D_/128, B_/128, H_), 256, SMEMM>>>(qh, ql, Wkh,
        pwq, nullptr, nullptr, nullptr, DH_, D_, D_, H_*D_, DH_, DH_, 0, D_, 128);
    // fused attention -> u fp16 hi/lo
    attn_k<<<B_, 256>>>(neighbors, lengths);
    // ctx[:, h*64+cc] = sum_c u[:,h*512+c] * WvT[h*128+cc, c] + bv — mma MODE 2
    gemm_mma<0,0,2,2><<<dim3(1, B_/128, H_), 256, SMEMM>>>(uh, ul, WvT,
        pctx, nullptr, nullptr, bv, D_, H_*D_, D_, D_, D_, 0, 128*D_, DH_, DH_);
    conv_split<<<BD/1024, 256>>>(pctx, ctxh, ctxl, BD);
    // out = ctx @ Wo + bo — 2-pass, split-K 4
    gemm_mma<0,0,2,1><<<dim3(D_/128, B_/128, 4), 256, SMEMM>>>(ctxh, ctxl, Woth,
        ppart, nullptr, nullptr, nullptr, D_/4, D_, D_, D_, 0,0,0,0, 128);
    reduce4_f32<<<BD/1024, 256>>>(ppart, out, bo, BD, D_);
}

// round 17
// speedup vs baseline: 1.2983x; 1.2983x over previous
#include <cuda_runtime.h>
#include <cuda_fp16.h>
#include <math.h>

#define B_   2048
#define N_   128
#define D_   512
#define HID_ 2048
#define H_   8
#define DH_  64

typedef unsigned long long ull;
typedef __half hf;

// ---------------- scratch ----------------
__device__ float g_q[B_*D_];
__device__ float g_wq[B_*H_*D_];
__device__ float g_u[B_*H_*D_];
__device__ float g_ctx[B_*D_];
__device__ float g_part[4*B_*D_];
__device__ float g_ps [16*HID_], g_psq[16*HID_];
__device__ float g_scale[HID_], g_shift[HID_];
__device__ float g_b2p[HID_];
__device__ float g_b2part[16*HID_];
__device__ float g_WkT[D_*D_];            // WkT[j][c] = Wk[c][j]

__device__ hf g_cath[B_*D_];
__device__ hf g_W1th[HID_*D_];
__device__ hf g_W2th[HID_*HID_];
__device__ hf g_X1h [B_*HID_];
__device__ hf g_X2h [B_*HID_];
__device__ hf g_W3th[D_*HID_];
__device__ hf g_embh[B_*D_],    g_embl[B_*D_];
__device__ hf g_Wqth[D_*D_];
__device__ hf g_Woth[D_*D_];
__device__ hf g_ctxh[B_*D_],    g_ctxl[B_*D_];

// ---------------- PTX helpers ----------------
__device__ __forceinline__ void ffma2(ull &d, ull a, ull b) {
    asm("fma.rn.f32x2 %0, %1, %2, %0;" : "+l"(d) : "l"(a), "l"(b));
}
__device__ __forceinline__ ull dup2(float v) {
    ull r; asm("mov.b64 %0, {%1, %1};" : "=l"(r) : "r"(__float_as_uint(v))); return r;
}
__device__ __forceinline__ float lo2(ull v) { return __uint_as_float((unsigned)v); }
__device__ __forceinline__ float hi2(ull v) { return __uint_as_float((unsigned)(v>>32)); }

__device__ __forceinline__ void mma16816(float* c, const unsigned* a, unsigned b0, unsigned b1) {
    asm volatile("mma.sync.aligned.m16n8k16.row.col.f32.f16.f16.f32 "
        "{%0,%1,%2,%3}, {%4,%5,%6,%7}, {%8,%9}, {%0,%1,%2,%3};"
        : "+f"(c[0]), "+f"(c[1]), "+f"(c[2]), "+f"(c[3])
        : "r"(a[0]), "r"(a[1]), "r"(a[2]), "r"(a[3]), "r"(b0), "r"(b1));
}
__device__ __forceinline__ void ldsm4(unsigned* r, unsigned a) {
    asm volatile("ldmatrix.sync.aligned.m8n8.x4.shared.b16 {%0,%1,%2,%3}, [%4];"
        : "=r"(r[0]), "=r"(r[1]), "=r"(r[2]), "=r"(r[3]) : "r"(a));
}
__device__ __forceinline__ void cpasync16(unsigned s, const void* g) {
    asm volatile("cp.async.cg.shared.global [%0], [%1], 16;" :: "r"(s), "l"(g));
}
#define CPCOMMIT() asm volatile("cp.async.commit_group;" ::: "memory")
#define CPWAIT0()  asm volatile("cp.async.wait_group 0;" ::: "memory")

__device__ __forceinline__ hf f2h(float v) { return __float2half_rn(v); }
__device__ __forceinline__ float h2f(hf v) { return __half2float(v); }

#define ASTR  40
#define OPTILE (128*ASTR)
#define BUFBF  (4*OPTILE)
#define BUFBYTES (BUFBF*2)
#define SMEMM  (2*BUFBYTES)

// ---------------- HMMA GEMM with optional split-K (round-15 version) ---------
template<int ACT, int OUTH, int PASSES, int SPLIT>
__global__ __launch_bounds__(256) void gemm_mma(
    const hf* __restrict__ Ah_, const hf* __restrict__ Al_,
    const hf* __restrict__ Bh_,
    float* __restrict__ Cf, hf* __restrict__ Ch, hf* __restrict__ Cl,
    const float* __restrict__ bias, int K, int ldK, int Nfull)
{
    extern __shared__ hf sm[];
    const int t = threadIdx.x, lane = t & 31, wid = t >> 5;
    const int wm = wid & 3, wn = wid >> 2;
    const int g = lane >> 2, tid4 = lane & 3;
    const int row0 = blockIdx.y * 128, col0 = blockIdx.x * 128;
    const int koff = SPLIT ? (blockIdx.z * K) : 0;
    const unsigned sbase = (unsigned)__cvta_generic_to_shared(sm);

    float acc[2][8][4];
#pragma unroll
    for (int i = 0; i < 2; i++)
#pragma unroll
        for (int j = 0; j < 8; j++)
#pragma unroll
            for (int k = 0; k < 4; k++) acc[i][j][k] = 0.f;

    const int lrow = t >> 1, lhalf = t & 1;
    const unsigned sdst = sbase + (unsigned)((lrow * ASTR) * 2) + lhalf * 32;
    auto issue = [&](int kc, int buf) {
        const size_t ga = (size_t)(row0 + lrow) * ldK + koff + kc * 32 + lhalf * 16;
        const size_t gb = (size_t)(col0 + lrow) * ldK + koff + kc * 32 + lhalf * 16;
        const unsigned d = sdst + buf * BUFBYTES;
        cpasync16(d,                 Ah_ + ga);
        cpasync16(d + 16,            Ah_ + ga + 8);
        if (PASSES >= 2) {
            cpasync16(d + OPTILE*2,      Al_ + ga);
            cpasync16(d + OPTILE*2 + 16, Al_ + ga + 8);
        }
        cpasync16(d + OPTILE*4,      Bh_ + gb);
        cpasync16(d + OPTILE*4 + 16, Bh_ + gb + 8);
    };

    const int arow_l = (lane & 7) + ((lane >> 3) & 1) * 8;
    const int acol_l = (lane >> 4) * 8;
    const unsigned a_base = sbase + (unsigned)(((wm * 32 + arow_l) * ASTR + acol_l) * 2);
    const int brow_l = (lane & 7) + (lane >> 4) * 8;
    const int bcol_l = ((lane >> 3) & 1) * 8;
    const unsigned b_base = sbase + (unsigned)(4 * OPTILE)
                          + (unsigned)(((wn * 64 + brow_l) * ASTR + bcol_l) * 2);

    const int nc = K >> 5;
    issue(0, 0);
    CPCOMMIT();
    CPWAIT0();
    __syncthreads();

    for (int c = 0; c < nc; c++) {
        const int p = c & 1;
        if (c + 1 < nc) { issue(c + 1, p ^ 1); CPCOMMIT(); }

        const unsigned ab = a_base + p * BUFBYTES;
        const unsigned bb = b_base + p * BUFBYTES;
#pragma unroll
        for (int ks = 0; ks < 2; ks++) {
            const unsigned ko = ks * 32;
            unsigned ah[2][4], al[2][4];
#pragma unroll
            for (int mt = 0; mt < 2; mt++) {
                ldsm4(ah[mt], ab + mt * (16 * ASTR * 2) + ko);
                if (PASSES >= 2)
                    ldsm4(al[mt], ab + OPTILE * 2 + mt * (16 * ASTR * 2) + ko);
            }
#pragma unroll
            for (int ntp = 0; ntp < 4; ntp++) {
                unsigned bh4[4];
                ldsm4(bh4, bb + ntp * (16 * ASTR * 2) + ko);
#pragma unroll
                for (int sub = 0; sub < 2; sub++) {
                    const int nt = ntp * 2 + sub;
#pragma unroll
                    for (int mt = 0; mt < 2; mt++) {
                        mma16816(acc[mt][nt], ah[mt], bh4[sub*2], bh4[sub*2+1]);
                        if (PASSES >= 2)
                            mma16816(acc[mt][nt], al[mt], bh4[sub*2], bh4[sub*2+1]);
                    }
                }
            }
        }
        if (c + 1 < nc) {
            CPWAIT0();
            __syncthreads();
        }
    }

    float* Cp = Cf;
    if (SPLIT) Cp += (size_t)blockIdx.z * (size_t)(gridDim.y * 128) * Nfull;

#pragma unroll
    for (int mt = 0; mt < 2; mt++) {
#pragma unroll
        for (int nt = 0; nt < 8; nt++) {
            const int r = row0 + wm * 32 + mt * 16 + g;
            const int cc = col0 + wn * 64 + nt * 8 + tid4 * 2;
            if (SPLIT) {
                *(float2*)(Cp + (size_t)r * Nfull + cc) =
                    make_float2(acc[mt][nt][0], acc[mt][nt][1]);
                *(float2*)(Cp + (size_t)(r + 8) * Nfull + cc) =
                    make_float2(acc[mt][nt][2], acc[mt][nt][3]);
                continue;
            }
            float v0 = acc[mt][nt][0] + bias[cc];
            float v1 = acc[mt][nt][1] + bias[cc + 1];
            float v2 = acc[mt][nt][2] + bias[cc];
            float v3 = acc[mt][nt][3] + bias[cc + 1];
            if (ACT) { v0 = tanhf(v0); v1 = tanhf(v1); v2 = tanhf(v2); v3 = tanhf(v3); }
            if (OUTH) {
                hf h0 = f2h(v0), h1 = f2h(v1), h2 = f2h(v2), h3 = f2h(v3);
                *(half2*)(Ch + (size_t)r * Nfull + cc)       = half2(h0, h1);
                *(half2*)(Ch + (size_t)(r + 8) * Nfull + cc) = half2(h2, h3);
                if (Cl) {
                    *(half2*)(Cl + (size_t)r * Nfull + cc) =
                        half2(f2h(v0 - h2f(h0)), f2h(v1 - h2f(h1)));
                    *(half2*)(Cl + (size_t)(r + 8) * Nfull + cc) =
                        half2(f2h(v2 - h2f(h2)), f2h(v3 - h2f(h3)));
                }
            } else {
                *(float2*)(Cp + (size_t)r * Nfull + cc)       = make_float2(v0, v1);
                *(float2*)(Cp + (size_t)(r + 8) * Nfull + cc) = make_float2(v2, v3);
            }
        }
    }
}

// ---------------- split-K reduces ----------------
__global__ __launch_bounds__(256) void reduce4_f32(const float* __restrict__ part,
                                                   float* __restrict__ out,
                                                   const float* __restrict__ bias,
                                                   int total, int ldc)
{
    const int i = (blockIdx.x * 256 + threadIdx.x) * 4;
    if (i >= total) return;
    float4 v0 = *(const float4*)(part + i);
    float4 v1 = *(const float4*)(part + (size_t)total   + i);
    float4 v2 = *(const float4*)(part + (size_t)total*2 + i);
    float4 v3 = *(const float4*)(part + (size_t)total*3 + i);
    const int c = i % ldc;
    float4 r;
    r.x = (v0.x + v1.x) + (v2.x + v3.x) + bias[c+0];
    r.y = (v0.y + v1.y) + (v2.y + v3.y) + bias[c+1];
    r.z = (v0.z + v1.z) + (v2.z + v3.z) + bias[c+2];
    r.w = (v0.w + v1.w) + (v2.w + v3.w) + bias[c+3];
    *(float4*)(out + i) = r;
}

__global__ __launch_bounds__(256) void reduce4_hilo(const float* __restrict__ part,
                                                    hf* __restrict__ oh, hf* __restrict__ ol,
                                                    const float* __restrict__ bias,
                                                    int total, int ldc)
{
    const int i = (blockIdx.x * 256 + threadIdx.x) * 4;
    if (i >= total) return;
    float4 v0 = *(const float4*)(part + i);
    float4 v1 = *(const float4*)(part + (size_t)total   + i);
    float4 v2 = *(const float4*)(part + (size_t)total*2 + i);
    float4 v3 = *(const float4*)(part + (size_t)total*3 + i);
    const int c = i % ldc;
    float r0 = (v0.x + v1.x) + (v2.x + v3.x) + bias[c+0];
    float r1 = (v0.y + v1.y) + (v2.y + v3.y) + bias[c+1];
    float r2 = (v0.z + v1.z) + (v2.z + v3.z) + bias[c+2];
    float r3 = (v0.w + v1.w) + (v2.w + v3.w) + bias[c+3];
    hf h0=f2h(r0), h1=f2h(r1), h2=f2h(r2), h3=f2h(r3);
    *(half2*)(oh+i)   = half2(h0,h1);
    *(half2*)(oh+i+2) = half2(h2,h3);
    *(half2*)(ol+i)   = half2(f2h(r0-h2f(h0)), f2h(r1-h2f(h1)));
    *(half2*)(ol+i+2) = half2(f2h(r2-h2f(h2)), f2h(r3-h2f(h3)));
}

// ---------------- conversions ----------------
__global__ __launch_bounds__(256) void conv_split(const float* __restrict__ in,
                                                  hf* __restrict__ oh, hf* __restrict__ ol, int n)
{
    const int i = (blockIdx.x * 256 + threadIdx.x) * 4;
    if (i >= n) return;
    float4 v = *(const float4*)(in + i);
    hf h0=f2h(v.x), h1=f2h(v.y), h2=f2h(v.z), h3=f2h(v.w);
    *(half2*)(oh+i)   = half2(h0,h1);
    *(half2*)(oh+i+2) = half2(h2,h3);
    if (ol) {
        *(half2*)(ol+i)   = half2(f2h(v.x-h2f(h0)), f2h(v.y-h2f(h1)));
        *(half2*)(ol+i+2) = half2(f2h(v.z-h2f(h2)), f2h(v.w-h2f(h3)));
    }
}

template<int SCALE>
__global__ __launch_bounds__(256) void conv_tsplit(const float* __restrict__ in,
                                                   hf* __restrict__ oh, int K, int N)
{
    __shared__ float tile[32][33];
    const int n0 = blockIdx.x * 32, k0 = blockIdx.y * 32;
    const int c = threadIdx.x & 31, r = threadIdx.x >> 5;
#pragma unroll
    for (int rr = 0; rr < 4; rr++)
        tile[r + rr*8][c] = in[(size_t)(k0 + r + rr*8) * N + n0 + c];
    __syncthreads();
    const float sck = SCALE ? g_scale[k0 + c] : 1.f;
#pragma unroll
    for (int rr = 0; rr < 4; rr++) {
        const int row = r + rr*8;
        oh[(size_t)(n0 + row) * K + k0 + c] = f2h(tile[c][row] * sck);
    }
}

// fp32 transpose: out[j][r] = in[r][j], in [R,C]
__global__ __launch_bounds__(256) void transpose_f32(const float* __restrict__ in,
                                                     float* __restrict__ out, int R, int C)
{
    __shared__ float tile[32][33];
    const int c0 = blockIdx.x * 32, r0 = blockIdx.y * 32;
    const int x = threadIdx.x & 31, y = threadIdx.x >> 5;
#pragma unroll
    for (int rr = 0; rr < 4; rr++)
        tile[y + rr*8][x] = in[(size_t)(r0 + y + rr*8) * C + c0 + x];
    __syncthreads();
#pragma unroll
    for (int rr = 0; rr < 4; rr++)
        out[(size_t)(c0 + y + rr*8) * R + r0 + x] = tile[x][y + rr*8];
}

// bias2' = b2 + shift @ W2 — two-stage
__global__ __launch_bounds__(256) void bias2_part(const float* __restrict__ W2)
{
    const int c = blockIdx.x * 256 + threadIdx.x;
    const int k0 = blockIdx.y * 128;
    float s = 0.f;
#pragma unroll 4
    for (int k = 0; k < 128; k++)
        s += g_shift[k0 + k] * W2[(size_t)(k0 + k) * HID_ + c];
    g_b2part[blockIdx.y * HID_ + c] = s;
}
__global__ __launch_bounds__(256) void bias2_fin(const float* __restrict__ b2)
{
    const int c = blockIdx.x * 256 + threadIdx.x;
    float s = b2[c];
#pragma unroll
    for (int i = 0; i < 16; i++) s += g_b2part[i * HID_ + c];
    g_b2p[c] = s;
}

// ---------------- BN ----------------
__global__ void bn_partial()
{
    const int t = threadIdx.x;
    const int col = blockIdx.x * 128 + (t & 127);
    const int rh = t >> 7;
    const int r0 = blockIdx.y * 128 + rh * 64;
    float s = 0.f, sq = 0.f;
    for (int r = 0; r < 64; r++) {
        float v = h2f(g_X1h[(size_t)(r0 + r) * HID_ + col]);
        s += v; sq += v * v;
    }
    __shared__ float sm1[256], sm2[256];
    sm1[t] = s; sm2[t] = sq;
    __syncthreads();
    if (rh == 0) {
        s += sm1[t+128]; sq += sm2[t+128];
        g_ps [blockIdx.y * HID_ + col] = s;
        g_psq[blockIdx.y * HID_ + col] = sq;
    }
}
__global__ void bn_finalize(const float* __restrict__ gamma, const float* __restrict__ beta)
{
    const int c = blockIdx.x * 256 + threadIdx.x;
    float s = 0.f, sq = 0.f;
    for (int i = 0; i < 16; i++) { s += g_ps[i*HID_+c]; sq += g_psq[i*HID_+c]; }
    const float mean = s * (1.f/(float)B_);
    const float var  = sq * (1.f/(float)B_) - mean*mean;
    const float sc = gamma[c] * rsqrtf(var + 1e-5f);
    g_scale[c] = sc;
    g_shift[c] = beta[c] - mean * sc;
}

// ---------------- FFMA2 SGEMM (wq / ctx only; TRB=0 coalesced) ---------------
template<int TRB>
__global__ __launch_bounds__(256, 2) void gemm_k(
    const float* __restrict__ A, int lda, const float* __restrict__ Bm, int ldb,
    float* __restrict__ C, int ldc, const float* __restrict__ bias,
    int M, int N, int K, int zA, int zB, int zC)
{
    __shared__ float Ast[2][8][132];
    __shared__ float Bs [2][8][132];
    const int t = threadIdx.x, tx = t & 15, ty = t >> 4;
    const int row0 = blockIdx.y * 128, col0 = blockIdx.x * 128;
    const int z = blockIdx.z;
    A += (size_t)z * zA; Bm += (size_t)z * zB; C += (size_t)z * zC;
    if (bias) bias += (size_t)z * zC;

    ull acc2[8][4];
#pragma unroll
    for (int i = 0; i < 8; i++)
#pragma unroll
        for (int j = 0; j < 4; j++) acc2[i][j] = 0ull;

    const int arow = t >> 1, ac = (t & 1) * 4;
    const int bk = t >> 5, bc = (t & 31) * 4;
    const float* Aptr = A + (size_t)(row0 + arow) * lda + ac;
    const int nk = K >> 3;

    auto ldB = [&](int k0, float4 &b4) {
        if (!TRB) {
            if (col0 + bc < N) b4 = *(const float4*)(Bm + (size_t)(k0 + bk) * ldb + col0 + bc);
            else b4 = make_float4(0.f,0.f,0.f,0.f);
        } else {
            const int c0 = col0 + bc;
            b4.x = (c0+0<N) ? Bm[(size_t)(c0+0)*ldb + k0 + bk] : 0.f;
            b4.y = (c0+1<N) ? Bm[(size_t)(c0+1)*ldb + k0 + bk] : 0.f;
            b4.z = (c0+2<N) ? Bm[(size_t)(c0+2)*ldb + k0 + bk] : 0.f;
            b4.w = (c0+3<N) ? Bm[(size_t)(c0+3)*ldb + k0 + bk] : 0.f;
        }
    };
    {
        float4 a4 = *(const float4*)(Aptr);
        float4 b4; ldB(0, b4);
        Ast[0][ac+0][arow]=a4.x; Ast[0][ac+1][arow]=a4.y; Ast[0][ac+2][arow]=a4.z; Ast[0][ac+3][arow]=a4.w;
        Bs[0][bk][bc+0]=b4.x; Bs[0][bk][bc+1]=b4.y; Bs[0][bk][bc+2]=b4.z; Bs[0][bk][bc+3]=b4.w;
    }
    __syncthreads();

    int p = 0;
    for (int kt = 0; kt < nk; kt++) {
        const int k0 = (kt + 1) << 3;
        float4 a4n, b4n;
        if (kt + 1 < nk) { a4n = *(const float4*)(Aptr + k0); ldB(k0, b4n); }
#pragma unroll
        for (int kk = 0; kk < 8; kk++) {
            float af[8];
            *(float4*)&af[0] = *(const float4*)&Ast[p][kk][ty*4];
            *(float4*)&af[4] = *(const float4*)&Ast[p][kk][64 + ty*4];
            ull a2[8];
#pragma unroll
            for (int i = 0; i < 8; i++) a2[i] = dup2(af[i]);
            const ull* bp0 = (const ull*)&Bs[p][kk][tx*4];
            const ull* bp1 = (const ull*)&Bs[p][kk][64 + tx*4];
            ull b2[4] = {bp0[0], bp0[1], bp1[0], bp1[1]};
#pragma unroll
            for (int i = 0; i < 8; i++)
#pragma unroll
                for (int j = 0; j < 4; j++) ffma2(acc2[i][j], a2[i], b2[j]);
        }
        if (kt + 1 < nk) {
            const int q = p ^ 1;
            Ast[q][ac+0][arow]=a4n.x; Ast[q][ac+1][arow]=a4n.y; Ast[q][ac+2][arow]=a4n.z; Ast[q][ac+3][arow]=a4n.w;
            Bs[q][bk][bc+0]=b4n.x; Bs[q][bk][bc+1]=b4n.y; Bs[q][bk][bc+2]=b4n.z; Bs[q][bk][bc+3]=b4n.w;
        }
        __syncthreads();
        p ^= 1;
    }
#pragma unroll
    for (int i = 0; i < 8; i++) {
        const int r = row0 + ((i<4) ? (ty*4+i) : (64+ty*4+(i-4)));
        float av[8];
#pragma unroll
        for (int j = 0; j < 4; j++) { av[2*j]=lo2(acc2[i][j]); av[2*j+1]=hi2(acc2[i][j]); }
#pragma unroll
        for (int j = 0; j < 8; j++) {
            const int c = col0 + ((j<4) ? (tx*4+j) : (64+tx*4+(j-4)));
            if (c < N) {
                float v = av[j];
                if (bias) v += bias[c];
                C[(size_t)r * ldc + c] = v;
            }
        }
    }
}

// ---------------- fused single-pass attention (early exit on length) ---------
__global__ __launch_bounds__(256) void attn_k(const float* __restrict__ nb,
                                              const int* __restrict__ len)
{
    __shared__ float nbt[8 * 544];
    __shared__ float ssum[H_][4];
    const int b = blockIdx.x, t = threadIdx.x;
    const int w = t >> 5, l = t & 31;
    const int hg = w & 1, ng = w >> 1;
    const float* nbb = nb + (size_t)b * N_ * D_;
    const int L = len[b];
    const int ntiles = (L + 7) >> 3;

    float wqf[4][16];
#pragma unroll
    for (int hh = 0; hh < 4; hh++) {
        const float* p = g_wq + (size_t)b * H_ * D_ + (size_t)(hg*4+hh) * D_ + l*16;
#pragma unroll
        for (int j4 = 0; j4 < 4; j4++) {
            float4 v = *(const float4*)(p + j4*4);
            wqf[hh][j4*4+0]=v.x; wqf[hh][j4*4+1]=v.y; wqf[hh][j4*4+2]=v.z; wqf[hh][j4*4+3]=v.w;
        }
    }
    float acc[4][16], se[4];
#pragma unroll
    for (int hh = 0; hh < 4; hh++) { se[hh]=0.f;
#pragma unroll
        for (int j = 0; j < 16; j++) acc[hh][j]=0.f; }

    for (int tile = 0; tile < ntiles; tile++) {
        __syncthreads();
#pragma unroll
        for (int i = 0; i < 4; i++) {
            const int idx = t + i*256, rr = idx >> 7, c4 = idx & 127;
            float4 v = *(const float4*)(nbb + (size_t)(tile*8+rr)*D_ + (c4<<2));
            const int ph = rr*544 + (c4>>2)*17 + (c4&3)*4;
            nbt[ph+0]=v.x; nbt[ph+1]=v.y; nbt[ph+2]=v.z; nbt[ph+3]=v.w;
        }
        __syncthreads();
#pragma unroll
        for (int nn = 0; nn < 2; nn++) {
            const int nr = ng*2+nn, n_glob = tile*8+nr;
            const float* row = nbt + nr*544 + l*17;
            float rv[16];
#pragma unroll
            for (int j = 0; j < 16; j++) rv[j] = row[j];
            float p0=0.f,p1=0.f,p2=0.f,p3=0.f;
#pragma unroll
            for (int j = 0; j < 16; j++) {
                p0 += rv[j]*wqf[0][j]; p1 += rv[j]*wqf[1][j];
                p2 += rv[j]*wqf[2][j]; p3 += rv[j]*wqf[3][j];
            }
#pragma unroll
            for (int off = 16; off; off >>= 1) {
                p0 += __shfl_xor_sync(0xffffffffu,p0,off); p1 += __shfl_xor_sync(0xffffffffu,p1,off);
                p2 += __shfl_xor_sync(0xffffffffu,p2,off); p3 += __shfl_xor_sync(0xffffffffu,p3,off);
            }
            const bool valid = (n_glob < L);
            const float e0 = valid ? __expf(p0*0.125f) : 0.f;
            const float e1 = valid ? __expf(p1*0.125f) : 0.f;
            const float e2 = valid ? __expf(p2*0.125f) : 0.f;
            const float e3 = valid ? __expf(p3*0.125f) : 0.f;
            se[0]+=e0; se[1]+=e1; se[2]+=e2; se[3]+=e3;
#pragma unroll
            for (int j = 0; j < 16; j++) {
                acc[0][j]+=e0*rv[j]; acc[1][j]+=e1*rv[j];
                acc[2][j]+=e2*rv[j]; acc[3][j]+=e3*rv[j];
            }
        }
    }
    __syncthreads();
    if (l == 0)
#pragma unroll
        for (int hh = 0; hh < 4; hh++) ssum[hg*4+hh][ng] = se[hh];

    float* ur = nbt;
    __syncthreads();
    for (int r = 0; r < 4; r++) {
        if (ng == r) {
#pragma unroll
            for (int hh = 0; hh < 4; hh++)
#pragma unroll
                for (int j = 0; j < 16; j++) {
                    const int idx = (hg*4+hh)*D_ + l*16 + j;
                    if (r == 0) ur[idx] = acc[hh][j]; else ur[idx] += acc[hh][j];
                }
        }
        __syncthreads();
    }
    float* up = g_u + (size_t)b * H_ * D_;
    for (int i = t*4; i < H_ * D_; i += 1024) {
        const int h = i >> 9;
        const float inv = 1.f / (ssum[h][0]+ssum[h][1]+ssum[h][2]+ssum[h][3]);
        float4 v = *(const float4*)(ur + i);
        v.x*=inv; v.y*=inv; v.z*=inv; v.w*=inv;
        *(float4*)(up + i) = v;
    }
}

// ---------------- host ----------------
extern "C" void kernel_launch(void* const* d_in, const int* in_sizes, int n_in,
                              void* d_out, int out_size)
{
    const float* catalog  = (const float*)d_in[0];
    const float* neighbors= (const float*)d_in[1];
    const int*   lengths  = (const int*)  d_in[2];
    const float* W1 = (const float*)d_in[3];
    const float* b1 = (const float*)d_in[4];
    const float* gamma = (const float*)d_in[5];
    const float* beta  = (const float*)d_in[6];
    const float* W2 = (const float*)d_in[7];
    const float* b2 = (const float*)d_in[8];
    const float* W3 = (const float*)d_in[9];
    const float* b3 = (const float*)d_in[10];
    const float* Wq = (const float*)d_in[11];
    const float* bq = (const float*)d_in[12];
    const float* Wk = (const float*)d_in[13];
    // d_in[14] = bk cancels in softmax
    const float* Wv = (const float*)d_in[15];
    const float* bv = (const float*)d_in[16];
    const float* Wo = (const float*)d_in[17];
    const float* bo = (const float*)d_in[18];
    float* out = (float*)d_out;

    float *pq, *pwq, *pu, *pctx, *pb2p, *ppart, *pWkT;
    cudaGetSymbolAddress((void**)&pq,  g_q);
    cudaGetSymbolAddress((void**)&pwq, g_wq);
    cudaGetSymbolAddress((void**)&pu,  g_u);
    cudaGetSymbolAddress((void**)&pctx,g_ctx);
    cudaGetSymbolAddress((void**)&pb2p,g_b2p);
    cudaGetSymbolAddress((void**)&ppart,g_part);
    cudaGetSymbolAddress((void**)&pWkT, g_WkT);
    hf *cath,*W1th,*W2th,*X1h,*X2h,*W3th,*embh,*embl,*Wqth,*Woth,*ctxh,*ctxl;
    cudaGetSymbolAddress((void**)&cath, g_cath);
    cudaGetSymbolAddress((void**)&W1th, g_W1th);
    cudaGetSymbolAddress((void**)&W2th, g_W2th);
    cudaGetSymbolAddress((void**)&X1h,  g_X1h);
    cudaGetSymbolAddress((void**)&X2h,  g_X2h);
    cudaGetSymbolAddress((void**)&W3th, g_W3th);
    cudaGetSymbolAddress((void**)&embh, g_embh); cudaGetSymbolAddress((void**)&embl, g_embl);
    cudaGetSymbolAddress((void**)&Wqth, g_Wqth);
    cudaGetSymbolAddress((void**)&Woth, g_Woth);
    cudaGetSymbolAddress((void**)&ctxh, g_ctxh); cudaGetSymbolAddress((void**)&ctxl, g_ctxl);

    cudaFuncSetAttribute(gemm_mma<1,1,1,0>, cudaFuncAttributeMaxDynamicSharedMemorySize, SMEMM);
    cudaFuncSetAttribute(gemm_mma<0,0,1,1>, cudaFuncAttributeMaxDynamicSharedMemorySize, SMEMM);
    cudaFuncSetAttribute(gemm_mma<0,0,2,1>, cudaFuncAttributeMaxDynamicSharedMemorySize, SMEMM);

    const int BD = B_ * D_;

    // weight/input conversions (hi-only; W2 deferred for BN fold)
    conv_tsplit<0><<<dim3(HID_/32, D_/32), 256>>>(W1, W1th, D_, HID_);
    conv_tsplit<0><<<dim3(D_/32, HID_/32), 256>>>(W3, W3th, HID_, D_);
    conv_tsplit<0><<<dim3(D_/32, D_/32), 256>>>(Wq, Wqth, D_, D_);
    conv_tsplit<0><<<dim3(D_/32, D_/32), 256>>>(Wo, Woth, D_, D_);
    transpose_f32<<<dim3(D_/32, D_/32), 256>>>(Wk, pWkT, D_, D_);
    conv_split<<<BD/1024, 256>>>(catalog, cath, nullptr, BD);

    // X1 = tanh(cat @ W1 + b1) -> fp16 hi (1-pass)
    gemm_mma<1,1,1,0><<<dim3(HID_/128, B_/128), 256, SMEMM>>>(cath, nullptr, W1th,
        nullptr, X1h, nullptr, b1, D_, D_, HID_);
    // BN stats
    bn_partial<<<dim3(16,16), 256>>>();
    bn_finalize<<<8, 256>>>(gamma, beta);
    // fold BN into W2 + bias
    conv_tsplit<1><<<dim3(HID_/32, HID_/32), 256>>>(W2, W2th, HID_, HID_);
    bias2_part<<<dim3(HID_/256, 16), 256>>>(W2);
    bias2_fin<<<HID_/256, 256>>>(b2);
    // X2 = tanh(X1 @ W2' + b2') -> fp16 hi (1-pass)
    gemm_mma<1,1,1,0><<<dim3(HID_/128, B_/128), 256, SMEMM>>>(X1h, nullptr, W2th,
        nullptr, X2h, nullptr, pb2p, HID_, HID_, HID_);
    // emb = X2 @ W3 + b3 — 1-pass, split-K 4, grid 256
    gemm_mma<0,0,1,1><<<dim3(D_/128, B_/128, 4), 256, SMEMM>>>(X2h, nullptr, W3th,
        ppart, nullptr, nullptr, nullptr, HID_/4, HID_, D_);
    reduce4_hilo<<<BD/1024, 256>>>(ppart, embh, embl, b3, BD, D_);
    // q = emb @ Wq + bq — 2-pass (emb hi/lo), split-K 4
    gemm_mma<0,0,2,1><<<dim3(D_/128, B_/128, 4), 256, SMEMM>>>(embh, embl, Wqth,
        ppart, nullptr, nullptr, nullptr, D_/4, D_, D_);
    reduce4_f32<<<BD/1024, 256>>>(ppart, pq, bq, BD, D_);
    // wq_eff[:,h,:] = q[:,h,:] @ WkT_h  — coalesced TRB=0 (WkT[h*64+k][c]), z over heads
    gemm_k<0><<<dim3(4,16,8), 256>>>(pq, D_, pWkT, D_, pwq, H_*D_, nullptr,
                                     B_, D_, DH_, DH_, DH_*D_, D_);
    attn_k<<<B_, 256>>>(neighbors, lengths);
    // ctx[:, h*64:] = u[:,h,:] @ Wv_h + bv_h
    gemm_k<0><<<dim3(1,16,8), 256>>>(pu, H_*D_, Wv, D_, pctx, D_, bv,
                                     B_, DH_, D_, D_, DH_, DH_);
    conv_split<<<BD/1024, 256>>>(pctx, ctxh, ctxl, BD);
    // out = ctx @ Wo + bo — 2-pass (ctx hi/lo), split-K 4
    gemm_mma<0,0,2,1><<<dim3(D_/128, B_/128, 4), 256, SMEMM>>>(ctxh, ctxl, Woth,
        ppart, nullptr, nullptr, nullptr, D_/4, D_, D_);
    reduce4_f32<<<BD/1024, 256>>>(ppart, out, bo, BD, D_);
}